// round 17
// baseline (speedup 1.0000x reference)
#include <cuda_runtime.h>
#include <cuda_bf16.h>
#include <cstdint>

#define B_ 2
#define L_ 2048
#define D_ 1024
#define H_ 8
#define QK_ 128
#define V_ 128
#define ML_ (B_*L_)        // 4096 rows
#define NBIG 4096          // q|k|v|g column blocks
#define K3 3072            // tripled K for split-bf16

// ---------------- scratch (device globals: no allocation allowed) ----------------
__device__ __nv_bfloat16 g_acat[(long)ML_ * K3];    // seq split [Ah|Ah|Al]
__device__ __nv_bfloat16 g_bcat[(long)K3 * NBIG];   // weights split [Bh;Bl;Bh], [k][n]
__device__ __nv_bfloat16 g_a2[(long)ML_ * K3];      // gate*rn split
__device__ __nv_bfloat16 g_b2[(long)K3 * 1024];     // w_o split, [k][n]
__device__ float g_c[(long)ML_ * NBIG];             // fused projection output [q|k|v|g]
__device__ float g_r[(long)ML_ * 1024];             // retention result (b,l,h,v)
// hi/lo split, roped q/k and v: layout [(h*B+b)*L + l][128]
__device__ __nv_bfloat16 g_qh[(long)H_*B_*L_*128];
__device__ __nv_bfloat16 g_ql[(long)H_*B_*L_*128];
__device__ __nv_bfloat16 g_kh[(long)H_*B_*L_*128];
__device__ __nv_bfloat16 g_kl[(long)H_*B_*L_*128];
__device__ __nv_bfloat16 g_vh[(long)H_*B_*L_*128];
__device__ __nv_bfloat16 g_vl[(long)H_*B_*L_*128];

// ---------------- mma helpers ----------------
__device__ __forceinline__ uint32_t smem_u32(const void* p) {
    return (uint32_t)__cvta_generic_to_shared(p);
}
__device__ __forceinline__ void ldmA(uint32_t* r, uint32_t addr) {
    asm volatile("ldmatrix.sync.aligned.m8n8.x4.shared.b16 {%0,%1,%2,%3}, [%4];"
                 : "=r"(r[0]), "=r"(r[1]), "=r"(r[2]), "=r"(r[3]) : "r"(addr));
}
__device__ __forceinline__ void ldmBT(uint32_t* r, uint32_t addr) {
    asm volatile("ldmatrix.sync.aligned.m8n8.x4.trans.shared.b16 {%0,%1,%2,%3}, [%4];"
                 : "=r"(r[0]), "=r"(r[1]), "=r"(r[2]), "=r"(r[3]) : "r"(addr));
}
__device__ __forceinline__ void mma16816(float* c, const uint32_t* a, const uint32_t* b) {
    asm volatile("mma.sync.aligned.m16n8k16.row.col.f32.bf16.bf16.f32 "
                 "{%0,%1,%2,%3},{%4,%5,%6,%7},{%8,%9},{%0,%1,%2,%3};"
                 : "+f"(c[0]), "+f"(c[1]), "+f"(c[2]), "+f"(c[3])
                 : "r"(a[0]), "r"(a[1]), "r"(a[2]), "r"(a[3]), "r"(b[0]), "r"(b[1]));
}
__device__ __forceinline__ void cp16(void* s, const void* gp) {
    uint32_t a = smem_u32(s);
    asm volatile("cp.async.cg.shared.global [%0], [%1], 16;" :: "r"(a), "l"(gp));
}
#define CP_COMMIT() asm volatile("cp.async.commit_group;")
#define CP_WAIT0()  asm volatile("cp.async.wait_group 0;")
#define CP_WAIT1()  asm volatile("cp.async.wait_group 1;")

// ---------------- pipelined bf16 tensor-core GEMM: C[M,N] = A[M,K3] * B[K3,N] ----------------
// 128x256 block tile, 8 warps (2x4), 64x64 warp tile, BK=64, 3-stage cp.async,
// single barrier per slab.
#define GSTAGES 3
#define G_AS 9216            // 128*72 bf16 per stage (A, pitch 72)
#define G_BS 16896           // 64*264 bf16 per stage (B, pitch 264)
#define G_STAGE (G_AS + G_BS)
#define GEMM_SMEM (GSTAGES * G_STAGE * 2)   // 156672 bytes

__device__ __forceinline__ void g_stage(__nv_bfloat16* smg, int buf, int tid,
    const __nv_bfloat16* A, const __nv_bfloat16* Bp, long m0, int n0, int Kdim, int ldb, int k0)
{
    __nv_bfloat16* sA = smg + buf * G_STAGE;
    __nv_bfloat16* sB = sA + G_AS;
    #pragma unroll
    for (int rep = 0; rep < 4; rep++) {            // A: 128 rows x 64 cols
        int idx = tid + rep * 256;
        int r = idx >> 3, c = (idx & 7) << 3;
        cp16(sA + r * 72 + c, A + (m0 + r) * (long)Kdim + k0 + c);
    }
    #pragma unroll
    for (int rep = 0; rep < 8; rep++) {            // B: 64 rows x 256 cols
        int idx = tid + rep * 256;
        int r = idx >> 5, c = (idx & 31) << 3;
        cp16(sB + r * 264 + c, Bp + (long)(k0 + r) * ldb + n0 + c);
    }
}

__global__ __launch_bounds__(256, 1) void gemm_bf16(float* __restrict__ Cext, int which,
                                                    int Kdim, int ldb, int ldc)
{
    extern __shared__ __nv_bfloat16 smg[];
    const __nv_bfloat16* A  = (which == 0) ? g_acat : g_a2;
    const __nv_bfloat16* Bp = (which == 0) ? g_bcat : g_b2;
    float* C = (which == 0) ? g_c : Cext;

    const int tid = threadIdx.x;
    const int warp = tid >> 5, lane = tid & 31;
    const int wm = (warp >> 2) * 64;        // 2 warps in M
    const int wn = (warp & 3) * 64;         // 4 warps in N
    const long m0 = (long)blockIdx.y * 128;
    const int  n0 = blockIdx.x * 256;

    const int KT = Kdim >> 6;   // 48 slabs of 64

    g_stage(smg, 0, tid, A, Bp, m0, n0, Kdim, ldb, 0);
    CP_COMMIT();
    g_stage(smg, 1, tid, A, Bp, m0, n0, Kdim, ldb, 64);
    CP_COMMIT();

    float acc[4][8][4] = {};
    int buf = 0;

    for (int kt = 0; kt < KT; kt++) {
        if (kt < KT - 1) CP_WAIT1(); else CP_WAIT0();
        __syncthreads();

        int nk = kt + 2;
        if (nk < KT) {
            int nb = buf + 2; if (nb >= GSTAGES) nb -= GSTAGES;
            g_stage(smg, nb, tid, A, Bp, m0, n0, Kdim, ldb, nk << 6);
            CP_COMMIT();
        }

        __nv_bfloat16* sA = smg + buf * G_STAGE;
        __nv_bfloat16* sB = sA + G_AS;

        #pragma unroll
        for (int ks = 0; ks < 64; ks += 16) {
            uint32_t af[4][4], bfr[4][4];
            #pragma unroll
            for (int mi = 0; mi < 4; mi++)
                ldmA(af[mi], smem_u32(sA + (wm + 16 * mi + (lane & 15)) * 72 + ks + ((lane >> 4) << 3)));
            #pragma unroll
            for (int nn = 0; nn < 4; nn++)
                ldmBT(bfr[nn], smem_u32(sB + (ks + (lane & 15)) * 264 + wn + 16 * nn + ((lane >> 4) << 3)));
            #pragma unroll
            for (int mi = 0; mi < 4; mi++)
                #pragma unroll
                for (int ni = 0; ni < 8; ni++)
                    mma16816(acc[mi][ni], af[mi], &bfr[ni >> 1][(ni & 1) << 1]);
        }
        // no trailing sync: next iteration's top barrier orders buffer reuse
        if (++buf == GSTAGES) buf = 0;
    }

    const int g = lane >> 2, t = lane & 3;
    #pragma unroll
    for (int mi = 0; mi < 4; mi++)
        #pragma unroll
        for (int ni = 0; ni < 8; ni++) {
            long row = m0 + wm + 16 * mi + g;
            int  col = n0 + wn + 8 * ni + 2 * t;
            *reinterpret_cast<float2*>(&C[row * (long)ldc + col]) =
                make_float2(acc[mi][ni][0], acc[mi][ni][1]);
            *reinterpret_cast<float2*>(&C[(row + 8) * (long)ldc + col]) =
                make_float2(acc[mi][ni][2], acc[mi][ni][3]);
        }
}

// ---------------- split fp32 -> [hi|hi|lo] bf16 (seq) ----------------
__global__ __launch_bounds__(256) void split_seq(const float* __restrict__ seq)
{
    long i = (long)blockIdx.x * 256 + threadIdx.x;
    int m = (int)(i >> 10), k = (int)(i & 1023);
    float x = seq[i];
    __nv_bfloat16 h = __float2bfloat16_rn(x);
    __nv_bfloat16 l = __float2bfloat16_rn(x - __bfloat162float(h));
    long base = (long)m * K3 + k;
    g_acat[base] = h; g_acat[base + 1024] = h; g_acat[base + 2048] = l;
}

__global__ __launch_bounds__(256) void pack_w(const float* __restrict__ wq,
                                              const float* __restrict__ wk,
                                              const float* __restrict__ wv,
                                              const float* __restrict__ wg)
{
    long i = (long)blockIdx.x * 256 + threadIdx.x;
    int k = (int)(i >> 12), n = (int)(i & 4095);
    float x;
    if (n < 1024)       x = wq[((n >> 7) << 17) + (k << 7) + (n & 127)];
    else if (n < 2048)  x = wk[(((n - 1024) >> 7) << 17) + (k << 7) + (n & 127)];
    else if (n < 3072)  x = wv[(((n - 2048) >> 7) << 17) + (k << 7) + (n & 127)];
    else                x = wg[(k << 10) + (n - 3072)];
    __nv_bfloat16 h = __float2bfloat16_rn(x);
    __nv_bfloat16 l = __float2bfloat16_rn(x - __bfloat162float(h));
    long base = (long)k * NBIG + n;
    g_bcat[base] = h;
    g_bcat[base + (long)1024 * NBIG] = l;
    g_bcat[base + (long)2048 * NBIG] = h;
}

__global__ __launch_bounds__(256) void pack_wo(const float* __restrict__ wo)
{
    long i = (long)blockIdx.x * 256 + threadIdx.x;
    int k = (int)(i >> 10), n = (int)(i & 1023);
    float x = wo[i];
    __nv_bfloat16 h = __float2bfloat16_rn(x);
    __nv_bfloat16 l = __float2bfloat16_rn(x - __bfloat162float(h));
    long base = (long)k * 1024 + n;
    g_b2[base] = h;
    g_b2[base + 1024L * 1024] = l;
    g_b2[base + 2048L * 1024] = h;
}

// ---------------- prep: rope(q,k) + hi/lo split of q,k,v into retention layout ----------------
__device__ __forceinline__ void split2(__nv_bfloat16* ph, __nv_bfloat16* pl, float x0, float x1)
{
    __nv_bfloat16 h0 = __float2bfloat16_rn(x0), h1 = __float2bfloat16_rn(x1);
    __nv_bfloat16 l0 = __float2bfloat16_rn(x0 - __bfloat162float(h0));
    __nv_bfloat16 l1 = __float2bfloat16_rn(x1 - __bfloat162float(h1));
    __nv_bfloat162 hv; hv.x = h0; hv.y = h1;
    __nv_bfloat162 lv; lv.x = l0; lv.y = l1;
    *reinterpret_cast<__nv_bfloat162*>(ph) = hv;
    *reinterpret_cast<__nv_bfloat162*>(pl) = lv;
}

__global__ __launch_bounds__(256) void prep_kernel(const float* __restrict__ times)
{
    int idx = blockIdx.x * 256 + threadIdx.x;   // over ML_*H_*64
    int p = idx & 63;
    int h = (idx >> 6) & 7;
    int m = idx >> 9;
    int b = m >> 11, l = m & 2047;

    float t = times[m];
    float theta = exp2f(-13.287712379549449f * (float)p * (1.0f / 64.0f));
    float s, c;
    sincosf(t * theta, &s, &c);

    long cb = (long)m * NBIG + (h << 7) + (p << 1);
    float q0 = g_c[cb], q1 = g_c[cb + 1];
    float k0 = g_c[cb + 1024], k1 = g_c[cb + 1025];
    float v0 = g_c[cb + 2048], v1 = g_c[cb + 2049];
    float Q0 = c * q0 - s * q1, Q1 = c * q1 + s * q0;
    float K0 = c * k0 + s * k1, K1 = c * k1 - s * k0;

    long ob = ((long)((h * B_ + b) * L_ + l) << 7) + (p << 1);
    split2(g_qh + ob, g_ql + ob, Q0, Q1);
    split2(g_kh + ob, g_kl + ob, K0, K1);
    split2(g_vh + ob, g_vl + ob, v0, v1);
}

// ---------------- tensor-core retention (unchanged, proven) ----------------
#define TQ 8704
#define OFF_QL 8704
#define OFF_KV 17408
#define KVSTRIDE 34816
#define OFF_SH 87040
#define OFF_SL 91648
#define RET_SMEM (96256 * 2)

__device__ __forceinline__ void stage_kv(__nv_bfloat16* sm, int buf, int tid,
    const __nv_bfloat16* Kh, const __nv_bfloat16* Kl,
    const __nv_bfloat16* Vh, const __nv_bfloat16* Vl, int j0)
{
    __nv_bfloat16* dst = sm + OFF_KV + buf * KVSTRIDE;
    #pragma unroll
    for (int rep = 0; rep < 4; rep++) {
        int idx = tid + rep * 256;
        int row = idx >> 4, c8 = (idx & 15) << 3;
        long go = (long)(j0 + row) * 128 + c8;
        int so = row * 136 + c8;
        cp16(dst + so,          Kh + go);
        cp16(dst + TQ + so,     Kl + go);
        cp16(dst + 2 * TQ + so, Vh + go);
        cp16(dst + 3 * TQ + so, Vl + go);
    }
}

__global__ __launch_bounds__(256) void retention_mma()
{
    extern __shared__ __nv_bfloat16 sm[];
    const int h = blockIdx.z, b = blockIdx.y;
    const int it = gridDim.x - 1 - blockIdx.x;   // heavy tiles first
    const int i0 = it * 64;
    const int nj = it + 1;

    const long hb = (long)(h * B_ + b) * L_ * 128;
    const __nv_bfloat16* Qh = g_qh + hb;
    const __nv_bfloat16* Ql = g_ql + hb;
    const __nv_bfloat16* Kh = g_kh + hb;
    const __nv_bfloat16* Kl = g_kl + hb;
    const __nv_bfloat16* Vh = g_vh + hb;
    const __nv_bfloat16* Vl = g_vl + hb;

    const int tid = threadIdx.x, warp = tid >> 5, lane = tid & 31;
    const int g = lane >> 2, t = lane & 3;

    const float gamma = 1.0f - exp2f(-5.0f - (float)h);
    const float lg = log2f(gamma);

    const int wm1 = (warp >> 1) << 4, wn1 = (warp & 1) << 5;
    const int wm2 = wm1,              wn2 = (warp & 1) << 6;

    float pr[2], pc[4][2];
    pr[0] = exp2f(lg * (float)(wm1 + g));
    pr[1] = exp2f(lg * (float)(wm1 + g + 8));
    const float invg = exp2f(-lg);
    #pragma unroll
    for (int ni = 0; ni < 4; ni++) {
        int c0 = wn1 + 8 * ni + 2 * t;
        pc[ni][0] = exp2f(-lg * (float)c0);
        pc[ni][1] = pc[ni][0] * invg;
    }

    #pragma unroll
    for (int rep = 0; rep < 4; rep++) {
        int idx = tid + rep * 256;
        int row = idx >> 4, c8 = (idx & 15) << 3;
        long go = (long)(i0 + row) * 128 + c8;
        int so = row * 136 + c8;
        cp16(sm + so, Qh + go);
        cp16(sm + OFF_QL + so, Ql + go);
    }
    stage_kv(sm, 0, tid, Kh, Kl, Vh, Vl, 0);
    CP_COMMIT();

    float accO[8][4] = {};
    __nv_bfloat16* sSH = sm + OFF_SH;
    __nv_bfloat16* sSL = sm + OFF_SL;

    for (int jt = 0; jt < nj; jt++) {
        CP_WAIT0();
        __syncthreads();
        int cur = jt & 1;
        if (jt + 1 < nj) { stage_kv(sm, cur ^ 1, tid, Kh, Kl, Vh, Vl, (jt + 1) * 64); CP_COMMIT(); }

        __nv_bfloat16* sKh = sm + OFF_KV + cur * KVSTRIDE;
        __nv_bfloat16* sKl = sKh + TQ;
        __nv_bfloat16* sVh = sKh + 2 * TQ;
        __nv_bfloat16* sVl = sKh + 3 * TQ;

        float accS[4][4] = {};
        #pragma unroll
        for (int pass = 0; pass < 3; pass++) {
            const __nv_bfloat16* Ap = (pass == 2) ? (sm + OFF_QL) : sm;
            const __nv_bfloat16* Bp = (pass == 1) ? sKl : sKh;
            #pragma unroll
            for (int k16 = 0; k16 < 8; k16++) {
                uint32_t a[4];
                ldmA(a, smem_u32(Ap + (wm1 + (lane & 15)) * 136 + k16 * 16 + ((lane >> 4) << 3)));
                uint32_t bk[2][4];
                #pragma unroll
                for (int nn = 0; nn < 2; nn++)
                    ldmA(bk[nn], smem_u32(Bp + (wn1 + 16 * nn + (lane & 15)) * 136 + k16 * 16 + ((lane >> 4) << 3)));
                #pragma unroll
                for (int ni = 0; ni < 4; ni++) {
                    uint32_t bb[2] = { bk[ni >> 1][ni & 1], bk[ni >> 1][(ni & 1) + 2] };
                    mma16816(accS[ni], a, bb);
                }
            }
        }

        const float base = exp2f(lg * (float)((it - jt) * 64));
        const bool diag = (jt == it);
        #pragma unroll
        for (int ni = 0; ni < 4; ni++) {
            int c0 = wn1 + 8 * ni + 2 * t;
            int r0 = wm1 + g;
            float s00 = accS[ni][0] * (base * pr[0] * pc[ni][0]);
            float s01 = accS[ni][1] * (base * pr[0] * pc[ni][1]);
            float s10 = accS[ni][2] * (base * pr[1] * pc[ni][0]);
            float s11 = accS[ni][3] * (base * pr[1] * pc[ni][1]);
            if (diag) {
                if (c0 > r0)         s00 = 0.0f;
                if (c0 + 1 > r0)     s01 = 0.0f;
                if (c0 > r0 + 8)     s10 = 0.0f;
                if (c0 + 1 > r0 + 8) s11 = 0.0f;
            }
            split2(sSH + r0 * 72 + c0,       sSL + r0 * 72 + c0,       s00, s01);
            split2(sSH + (r0 + 8) * 72 + c0, sSL + (r0 + 8) * 72 + c0, s10, s11);
        }
        __syncthreads();

        #pragma unroll
        for (int pass = 0; pass < 3; pass++) {
            const __nv_bfloat16* Sp = (pass == 2) ? sSL : sSH;
            const __nv_bfloat16* Vp = (pass == 1) ? sVl : sVh;
            #pragma unroll
            for (int k16 = 0; k16 < 4; k16++) {
                uint32_t a[4];
                ldmA(a, smem_u32(Sp + (wm2 + (lane & 15)) * 72 + k16 * 16 + ((lane >> 4) << 3)));
                uint32_t bv[4][4];
                #pragma unroll
                for (int nn = 0; nn < 4; nn++)
                    ldmBT(bv[nn], smem_u32(Vp + (k16 * 16 + (lane & 15)) * 136 + wn2 + 16 * nn + ((lane >> 4) << 3)));
                #pragma unroll
                for (int ni = 0; ni < 8; ni++)
                    mma16816(accO[ni], a, &bv[ni >> 1][(ni & 1) << 1]);
            }
        }
        __syncthreads();
    }

    #pragma unroll
    for (int ni = 0; ni < 8; ni++) {
        long row0 = (long)(b * L_ + i0 + wm2 + g);
        int col = wn2 + 8 * ni + 2 * t;
        *reinterpret_cast<float2*>(&g_r[(row0 * H_ + h) * 128 + col]) =
            make_float2(accO[ni][0], accO[ni][1]);
        *reinterpret_cast<float2*>(&g_r[((row0 + 8) * H_ + h) * 128 + col]) =
            make_float2(accO[ni][2], accO[ni][3]);
    }
}

// ---------------- fused groupnorm + silu gate + bf16 split ----------------
__global__ __launch_bounds__(256) void gnorm_gate_kernel(const float* __restrict__ gn_w,
                                                         const float* __restrict__ gn_b)
{
    int gidx = blockIdx.x * 8 + (threadIdx.x >> 5);   // group in [0, ML_*H_)
    int lane = threadIdx.x & 31;
    int h    = gidx & (H_ - 1);
    int m    = gidx >> 3;

    const float* p = g_r + (long)gidx * V_;
    float4 x = *reinterpret_cast<const float4*>(p + (lane << 2));

    float sum = x.x + x.y + x.z + x.w;
    #pragma unroll
    for (int off = 16; off; off >>= 1) sum += __shfl_xor_sync(~0u, sum, off);
    float mean = sum * (1.0f / 128.0f);

    float dx = x.x - mean, dy = x.y - mean, dz = x.z - mean, dw = x.w - mean;
    float sq = dx * dx + dy * dy + dz * dz + dw * dw;
    #pragma unroll
    for (int off = 16; off; off >>= 1) sq += __shfl_xor_sync(~0u, sq, off);
    float inv = rsqrtf(sq * (1.0f / 128.0f) + 1e-5f);

    const float* w  = gn_w + h * V_ + (lane << 2);
    const float* bb = gn_b + h * V_ + (lane << 2);
    float rn[4];
    rn[0] = dx * inv * w[0] + bb[0];
    rn[1] = dy * inv * w[1] + bb[1];
    rn[2] = dz * inv * w[2] + bb[2];
    rn[3] = dw * inv * w[3] + bb[3];

    const float* gp = g_c + (long)m * NBIG + 3072 + (h << 7) + (lane << 2);
    long base = (long)m * K3 + (h << 7) + (lane << 2);
    #pragma unroll
    for (int j = 0; j < 4; j += 2) {
        float gv0 = gp[j],     gv1 = gp[j + 1];
        float x0 = gv0 * rn[j]     / (1.0f + expf(-gv0));
        float x1 = gv1 * rn[j + 1] / (1.0f + expf(-gv1));
        split2(g_a2 + base + j + 1024, g_a2 + base + j + 2048, x0, x1);  // hi(dup), lo
        __nv_bfloat16 h0 = __float2bfloat16_rn(x0), h1 = __float2bfloat16_rn(x1);
        __nv_bfloat162 hv; hv.x = h0; hv.y = h1;
        *reinterpret_cast<__nv_bfloat162*>(g_a2 + base + j) = hv;
    }
}

// ---------------- launch ----------------
extern "C" void kernel_launch(void* const* d_in, const int* in_sizes, int n_in,
                              void* d_out, int out_size)
{
    const float* seq   = (const float*)d_in[0];
    const float* times = (const float*)d_in[1];
    const float* wq    = (const float*)d_in[2];
    const float* wk    = (const float*)d_in[3];
    const float* wv    = (const float*)d_in[4];
    const float* wg    = (const float*)d_in[5];
    const float* wo    = (const float*)d_in[6];
    const float* gnw   = (const float*)d_in[7];
    const float* gnb   = (const float*)d_in[8];
    float* out = (float*)d_out;

    cudaFuncSetAttribute(retention_mma, cudaFuncAttributeMaxDynamicSharedMemorySize, RET_SMEM);
    cudaFuncSetAttribute(gemm_bf16, cudaFuncAttributeMaxDynamicSharedMemorySize, GEMM_SMEM);

    split_seq<<<(ML_ * D_) / 256, 256>>>(seq);
    pack_w<<<(D_ * NBIG) / 256, 256>>>(wq, wk, wv, wg);
    pack_wo<<<(D_ * 1024) / 256, 256>>>(wo);

    // fused q|k|v|g projection: [4096 x 3072] @ [3072 x 4096] -> g_c
    gemm_bf16<<<dim3(NBIG / 256, ML_ / 128), 256, GEMM_SMEM>>>(nullptr, 0, K3, NBIG, NBIG);

    prep_kernel<<<(ML_ * H_ * 64) / 256, 256>>>(times);
    retention_mma<<<dim3(L_ / 64, B_, H_), 256, RET_SMEM>>>();
    gnorm_gate_kernel<<<(ML_ * H_) / 8, 256>>>(gnw, gnb);

    // output projection: [4096 x 3072] @ [3072 x 1024] -> d_out
    gemm_bf16<<<dim3(1024 / 256, ML_ / 128), 256, GEMM_SMEM>>>(out, 1, K3, 1024, 1024);
}